// round 4
// baseline (speedup 1.0000x reference)
#include <cuda_runtime.h>

#ifndef EPSF
#define EPSF 1e-07f
#endif

#define NTHREADS 256
#define MAXBLK   16384

static __device__ float        g_partials[MAXBLK];
static __device__ unsigned int g_count;   // zero at load; atomicInc wrap self-resets

__device__ __forceinline__ float ciou_term(float4 p, float4 t) {
    float px1 = p.x, py1 = p.y, px2 = p.z, py2 = p.w;
    float tx1 = t.x, ty1 = t.y, tx2 = t.z, ty2 = t.w;

    float iw = fmaxf(fminf(px2, tx2) - fmaxf(px1, tx1), 0.0f);
    float ih = fmaxf(fminf(py2, ty2) - fmaxf(py1, ty1), 0.0f);
    float inter = iw * ih;

    float pw = px2 - px1, ph = py2 - py1;
    float tw = tx2 - tx1, th = ty2 - ty1;
    float iou = inter / (pw * ph + tw * th - inter + EPSF);

    float dcx = 0.5f * (px1 + px2) - 0.5f * (tx1 + tx2);
    float dcy = 0.5f * (py1 + py2) - 0.5f * (ty1 + ty2);
    float center_dist_sq = dcx * dcx + dcy * dcy;

    float cw = fmaxf(px2, tx2) - fminf(px1, tx1);
    float ch = fmaxf(py2, ty2) - fminf(py1, ty1);
    float c_diag_sq = cw * cw + ch * ch + EPSF;               // eps inside bbox_iou
    float center_term = center_dist_sq / (c_diag_sq + EPSF);  // eps again in forward()

    float sw = (pw - tw) / (tw + EPSF);
    float sh = (ph - th) / (th + EPSF);

    return (1.0f - iou) + 2.0f * center_term + (sw * sw + sh * sh);
}

__global__ void __launch_bounds__(NTHREADS, 6)
ciou_fused_kernel(const float4* __restrict__ pred,
                  const float4* __restrict__ targ,
                  float* __restrict__ out,
                  int n) {
    const int i = blockIdx.x * NTHREADS + threadIdx.x;

    float local = 0.0f;
    if (i < n) {
        float4 p = __ldcs(&pred[i]);
        float4 t = __ldcs(&targ[i]);
        local = ciou_term(p, t);
    }

    // intra-block reduce
    #pragma unroll
    for (int off = 16; off > 0; off >>= 1)
        local += __shfl_down_sync(0xFFFFFFFFu, local, off);

    __shared__ float warp_sums[NTHREADS / 32];
    int lane = threadIdx.x & 31;
    int wid  = threadIdx.x >> 5;
    if (lane == 0) warp_sums[wid] = local;
    __syncthreads();

    __shared__ bool amLast;
    if (threadIdx.x == 0) {
        float bsum = 0.0f;
        #pragma unroll
        for (int w = 0; w < NTHREADS / 32; w++) bsum += warp_sums[w];
        g_partials[blockIdx.x] = bsum;
        __threadfence();
        unsigned int pos = atomicInc(&g_count, gridDim.x - 1);
        amLast = (pos == gridDim.x - 1);
    }
    __syncthreads();

    if (amLast) {
        double v = 0.0;
        for (int j = threadIdx.x; j < gridDim.x; j += NTHREADS)
            v += (double)g_partials[j];
        #pragma unroll
        for (int off = 16; off > 0; off >>= 1)
            v += __shfl_down_sync(0xFFFFFFFFu, v, off);

        __shared__ double dsums[NTHREADS / 32];
        if (lane == 0) dsums[wid] = v;
        __syncthreads();
        if (threadIdx.x == 0) {
            double tot = 0.0;
            #pragma unroll
            for (int w = 0; w < NTHREADS / 32; w++) tot += dsums[w];
            out[0] = (float)(tot / (double)n);
        }
    }
}

extern "C" void kernel_launch(void* const* d_in, const int* in_sizes, int n_in,
                              void* d_out, int out_size) {
    const float4* pred = (const float4*)d_in[0];
    const float4* targ = (const float4*)d_in[1];
    int n = in_sizes[0] / 4;   // floats -> boxes

    int blocks = (n + NTHREADS - 1) / NTHREADS;   // one box per thread
    if (blocks > MAXBLK) blocks = MAXBLK;         // N=4.19M -> exactly 16384
    if (blocks < 1) blocks = 1;

    ciou_fused_kernel<<<blocks, NTHREADS>>>(pred, targ, (float*)d_out, n);
}

// round 5
// speedup vs baseline: 1.7213x; 1.7213x over previous
#include <cuda_runtime.h>

#ifndef EPSF
#define EPSF 1e-07f
#endif

#define NTHREADS 256
#define UNROLL   4
#define MAXBLK   8192

static __device__ float        g_partials[MAXBLK];
static __device__ unsigned int g_count;   // zero at load; atomicInc wrap self-resets

__device__ __forceinline__ float ciou_term(float4 p, float4 t) {
    float px1 = p.x, py1 = p.y, px2 = p.z, py2 = p.w;
    float tx1 = t.x, ty1 = t.y, tx2 = t.z, ty2 = t.w;

    float iw = fmaxf(fminf(px2, tx2) - fmaxf(px1, tx1), 0.0f);
    float ih = fmaxf(fminf(py2, ty2) - fmaxf(py1, ty1), 0.0f);
    float inter = iw * ih;

    float pw = px2 - px1, ph = py2 - py1;
    float tw = tx2 - tx1, th = ty2 - ty1;
    // all denominators here are >= ~1 given the input domain -> fast divide is safe
    float iou = __fdividef(inter, pw * ph + tw * th - inter + EPSF);

    float dcx = 0.5f * (px1 + px2) - 0.5f * (tx1 + tx2);
    float dcy = 0.5f * (py1 + py2) - 0.5f * (ty1 + ty2);
    float center_dist_sq = dcx * dcx + dcy * dcy;

    float cw = fmaxf(px2, tx2) - fminf(px1, tx1);
    float ch = fmaxf(py2, ty2) - fminf(py1, ty1);
    float c_diag_sq = cw * cw + ch * ch + EPSF;               // eps inside bbox_iou
    float center_term = __fdividef(center_dist_sq, c_diag_sq + EPSF);  // eps again

    float sw = __fdividef(pw - tw, tw + EPSF);
    float sh = __fdividef(ph - th, th + EPSF);

    return (1.0f - iou) + 2.0f * center_term + (sw * sw + sh * sh);
}

__global__ void __launch_bounds__(NTHREADS, 4)
ciou_fused_kernel(const float4* __restrict__ pred,
                  const float4* __restrict__ targ,
                  float* __restrict__ out,
                  int n) {
    const int stride = gridDim.x * NTHREADS;
    const int base   = blockIdx.x * NTHREADS + threadIdx.x;

    float local = 0.0f;

    if (base + (UNROLL - 1) * stride < n) {
        #pragma unroll
        for (int k = 0; k < UNROLL; k++) {
            int i = base + k * stride;
            local += ciou_term(pred[i], targ[i]);
        }
        for (int i = base + UNROLL * stride; i < n; i += stride)
            local += ciou_term(pred[i], targ[i]);
    } else {
        for (int i = base; i < n; i += stride)
            local += ciou_term(pred[i], targ[i]);
    }

    // intra-block reduce
    #pragma unroll
    for (int off = 16; off > 0; off >>= 1)
        local += __shfl_down_sync(0xFFFFFFFFu, local, off);

    __shared__ float warp_sums[NTHREADS / 32];
    int lane = threadIdx.x & 31;
    int wid  = threadIdx.x >> 5;
    if (lane == 0) warp_sums[wid] = local;
    __syncthreads();

    __shared__ bool amLast;
    if (threadIdx.x == 0) {
        float bsum = 0.0f;
        #pragma unroll
        for (int w = 0; w < NTHREADS / 32; w++) bsum += warp_sums[w];
        g_partials[blockIdx.x] = bsum;
        __threadfence();
        unsigned int pos = atomicInc(&g_count, gridDim.x - 1);
        amLast = (pos == gridDim.x - 1);
    }
    __syncthreads();

    if (amLast) {
        double v = 0.0;
        for (int j = threadIdx.x; j < gridDim.x; j += NTHREADS)
            v += (double)g_partials[j];
        #pragma unroll
        for (int off = 16; off > 0; off >>= 1)
            v += __shfl_down_sync(0xFFFFFFFFu, v, off);

        __shared__ double dsums[NTHREADS / 32];
        if (lane == 0) dsums[wid] = v;
        __syncthreads();
        if (threadIdx.x == 0) {
            double tot = 0.0;
            #pragma unroll
            for (int w = 0; w < NTHREADS / 32; w++) tot += dsums[w];
            out[0] = (float)(tot / (double)n);
        }
    }
}

extern "C" void kernel_launch(void* const* d_in, const int* in_sizes, int n_in,
                              void* d_out, int out_size) {
    const float4* pred = (const float4*)d_in[0];
    const float4* targ = (const float4*)d_in[1];
    int n = in_sizes[0] / 4;   // floats -> boxes

    int blocks = (n + NTHREADS * UNROLL - 1) / (NTHREADS * UNROLL);
    if (blocks > MAXBLK) blocks = MAXBLK;
    if (blocks < 1) blocks = 1;

    ciou_fused_kernel<<<blocks, NTHREADS>>>(pred, targ, (float*)d_out, n);
}

// round 6
// speedup vs baseline: 1.7232x; 1.0011x over previous
#include <cuda_runtime.h>

#ifndef EPSF
#define EPSF 1e-07f
#endif

#define NTHREADS 256
#define UNROLL   4
#define MAXBLK   8192

static __device__ float        g_partials[MAXBLK];
static __device__ unsigned int g_count;   // zero at load; atomicInc wrap self-resets

__device__ __forceinline__ float ciou_term(float4 p, float4 t) {
    float px1 = p.x, py1 = p.y, px2 = p.z, py2 = p.w;
    float tx1 = t.x, ty1 = t.y, tx2 = t.z, ty2 = t.w;

    float iw = fmaxf(fminf(px2, tx2) - fmaxf(px1, tx1), 0.0f);
    float ih = fmaxf(fminf(py2, ty2) - fmaxf(py1, ty1), 0.0f);
    float inter = iw * ih;

    float pw = px2 - px1, ph = py2 - py1;
    float tw = tx2 - tx1, th = ty2 - ty1;

    float d_iou = pw * ph + tw * th - inter + EPSF;   // union area + eps  (>= ~1)

    float dcx = 0.5f * (px1 + px2) - 0.5f * (tx1 + tx2);
    float dcy = 0.5f * (py1 + py2) - 0.5f * (ty1 + ty2);
    float center_dist_sq = dcx * dcx + dcy * dcy;

    float cw = fmaxf(px2, tx2) - fminf(px1, tx1);
    float ch = fmaxf(py2, ty2) - fminf(py1, ty1);
    float c_diag_sq = cw * cw + ch * ch + EPSF;       // eps inside bbox_iou
    float d_ctr = c_diag_sq + EPSF;                   // eps again in forward()

    // one reciprocal serves two divides: x/a = x*b*inv(ab), y/b = y*a*inv(ab)
    float inv12 = __fdividef(1.0f, d_iou * d_ctr);
    float iou         = inter * d_ctr * inv12;
    float center_term = center_dist_sq * d_iou * inv12;

    float d3 = tw + EPSF, d4 = th + EPSF;
    float inv34 = __fdividef(1.0f, d3 * d4);
    float sw = (pw - tw) * d4 * inv34;
    float sh = (ph - th) * d3 * inv34;

    return (1.0f - iou) + 2.0f * center_term + (sw * sw + sh * sh);
}

__global__ void __launch_bounds__(NTHREADS, 6)
ciou_fused_kernel(const float4* __restrict__ pred,
                  const float4* __restrict__ targ,
                  float* __restrict__ out,
                  int n) {
    const int stride = gridDim.x * NTHREADS;
    const int base   = blockIdx.x * NTHREADS + threadIdx.x;

    float local = 0.0f;

    if (base + (UNROLL - 1) * stride < n) {
        #pragma unroll
        for (int k = 0; k < UNROLL; k++) {
            int i = base + k * stride;
            local += ciou_term(pred[i], targ[i]);
        }
        for (int i = base + UNROLL * stride; i < n; i += stride)
            local += ciou_term(pred[i], targ[i]);
    } else {
        for (int i = base; i < n; i += stride)
            local += ciou_term(pred[i], targ[i]);
    }

    // intra-block reduce
    #pragma unroll
    for (int off = 16; off > 0; off >>= 1)
        local += __shfl_down_sync(0xFFFFFFFFu, local, off);

    __shared__ float warp_sums[NTHREADS / 32];
    int lane = threadIdx.x & 31;
    int wid  = threadIdx.x >> 5;
    if (lane == 0) warp_sums[wid] = local;
    __syncthreads();

    __shared__ bool amLast;
    if (threadIdx.x == 0) {
        float bsum = 0.0f;
        #pragma unroll
        for (int w = 0; w < NTHREADS / 32; w++) bsum += warp_sums[w];
        g_partials[blockIdx.x] = bsum;
        __threadfence();
        unsigned int pos = atomicInc(&g_count, gridDim.x - 1);
        amLast = (pos == gridDim.x - 1);
    }
    __syncthreads();

    if (amLast) {
        double v = 0.0;
        for (int j = threadIdx.x; j < gridDim.x; j += NTHREADS)
            v += (double)g_partials[j];
        #pragma unroll
        for (int off = 16; off > 0; off >>= 1)
            v += __shfl_down_sync(0xFFFFFFFFu, v, off);

        __shared__ double dsums[NTHREADS / 32];
        if (lane == 0) dsums[wid] = v;
        __syncthreads();
        if (threadIdx.x == 0) {
            double tot = 0.0;
            #pragma unroll
            for (int w = 0; w < NTHREADS / 32; w++) tot += dsums[w];
            out[0] = (float)(tot / (double)n);
        }
    }
}

extern "C" void kernel_launch(void* const* d_in, const int* in_sizes, int n_in,
                              void* d_out, int out_size) {
    const float4* pred = (const float4*)d_in[0];
    const float4* targ = (const float4*)d_in[1];
    int n = in_sizes[0] / 4;   // floats -> boxes

    int blocks = (n + NTHREADS * UNROLL - 1) / (NTHREADS * UNROLL);
    if (blocks > MAXBLK) blocks = MAXBLK;
    if (blocks < 1) blocks = 1;

    ciou_fused_kernel<<<blocks, NTHREADS>>>(pred, targ, (float*)d_out, n);
}